// round 16
// baseline (speedup 1.0000x reference)
#include <cuda_runtime.h>

#define BATCH 64
#define T 128
#define N 32
#define M 8
#define P 16
#define MA 34    // padded row stride (even -> float2-aligned rows)
#define NCH 16   // backward-scan chunks
#define CHS 8    // chunk size
#define NMA (N * MA)

// Global scratch
__device__ float g_muf[BATCH * T * N];
__device__ float g_mup[BATCH * T * N];
__device__ float g_Sigf[(size_t)BATCH * T * N * N];
__device__ float g_Sigp[(size_t)BATCH * T * N * N];
__device__ float g_J[(size_t)BATCH * (T - 1) * N * N];   // X_t = J_t^T
__device__ float g_M[(size_t)BATCH * (T - 1) * N * N];   // M_t
__device__ float g_c[(size_t)BATCH * (T - 1) * N];       // c_t
__device__ float g_OX[(size_t)BATCH * NCH * N * N];
__device__ float g_OM[(size_t)BATCH * NCH * N * N];
__device__ float g_Oc[(size_t)BATCH * NCH * N];
__device__ float g_eS[(size_t)BATCH * NCH * N * N];
__device__ float g_emu[(size_t)BATCH * NCH * N];
__device__ volatile int g_prog[BATCH];   // forward progress flags

// =====================================================================
// k_main: grid 148, 512 thr, 1 block/SM (one resident wave).
//   blocks 0..63  : forward Kalman filter (proven 997.3 body) + progress flags
//   blocks 64..147: J2 workers consuming (b,t) tasks as they become ready
// =====================================================================
__global__ __launch_bounds__(512, 1) void k_main(
    const float* __restrict__ Y, const float* __restrict__ U,
    const float* __restrict__ A, const float* __restrict__ Bm,
    const float* __restrict__ C, const float* __restrict__ mu0,
    const float* __restrict__ Sig0)
{
    __shared__ __align__(16) float sm[9632];
    const int tid = threadIdx.x;

    if (blockIdx.x < 64) {
        // ============================ FORWARD ROLE =======================
        const int b = blockIdx.x;
        float* sA0  = sm;            // [2][NMA]
        float* sC0  = sm + 2176;     // [2][P*MA]
        float* sB0  = sm + 3264;     // [2][N*M]
        float* sV   = sm + 3776;
        float* sZ   = sm + 4320;
        float* sCSp = sm + 4864;
        float* sSig = sm + 5408;
        float* sAS  = sm + 6496;
        float* sSigp= sm + 7584;
        float* sS   = sm + 8672;     // stride 18
        float* sX   = sm + 8960;
        float* syv  = sm + 9504;     // [2][P]
        float* suv  = sm + 9536;     // [2][M]
        float* smu  = sm + 9552;
        float* smup = sm + 9584;
        float* sd   = sm + 9616;

        // ---- init state + t=0 inputs ----
        if (tid < N) smu[tid] = mu0[tid];
        {
            int r = tid >> 4, c2 = tid & 15;
            *(float2*)(sSig + r * MA + 2 * c2) = ((const float2*)Sig0)[tid];
        }
        {
            const size_t bt = (size_t)b * T;
            const float2* Ab = (const float2*)(A + bt * (N * N));
            const float2* Cb = (const float2*)(C + bt * (P * N));
            const float2* Bb = (const float2*)(Bm + bt * (N * M));
            {
                int r = tid >> 4, c2 = tid & 15;
                *(float2*)(sA0 + r * MA + 2 * c2) = Ab[tid];
            }
            if (tid < 256) {
                int r = tid >> 4, c2 = tid & 15;
                *(float2*)(sC0 + r * MA + 2 * c2) = Cb[tid];
            }
            if (tid < 128) ((float2*)sB0)[tid] = Bb[tid];
            if (tid < P) syv[tid] = Y[bt * P + tid];
            if (tid < M) suv[tid] = U[bt * M + tid];
        }
        __syncthreads();

        for (int t = 0; t < T; t++) {
            const int cur = t & 1, nxt = cur ^ 1;
            const size_t bt = (size_t)b * T + t;
            const float* Ac = sA0 + cur * NMA;
            const float* Cc = sC0 + cur * (P * MA);
            const float* Bc = sB0 + cur * (N * M);
            const float* yc = syv + cur * P;
            const float* uc = suv + cur * M;

            // ===== R0: AS = A*Sig (2x2) | V = C*A (1x2) + mu_p =============
            if (tid < 256) {
                const int r0 = (tid >> 4) * 2, c0 = (tid & 15) * 2;
                const float2* Xr0 = (const float2*)(Ac + r0 * MA);
                const float2* Xr1 = (const float2*)(Ac + (r0 + 1) * MA);
                float a00 = 0, a01 = 0, a10 = 0, a11 = 0;
                #pragma unroll
                for (int k2 = 0; k2 < 16; k2++) {
                    float2 x0 = Xr0[k2], x1 = Xr1[k2];
                    float2 y0 = *(const float2*)(sSig + (2 * k2) * MA + c0);
                    float2 y1 = *(const float2*)(sSig + (2 * k2 + 1) * MA + c0);
                    a00 += x0.x * y0.x + x0.y * y1.x;  a01 += x0.x * y0.y + x0.y * y1.y;
                    a10 += x1.x * y0.x + x1.y * y1.x;  a11 += x1.x * y0.y + x1.y * y1.y;
                }
                *(float2*)(sAS + r0 * MA + c0) = make_float2(a00, a01);
                *(float2*)(sAS + (r0 + 1) * MA + c0) = make_float2(a10, a11);
            } else {
                const int id = tid - 256;
                const int i = id >> 4, j0 = (id & 15) * 2;
                const float2* Cr = (const float2*)(Cc + i * MA);
                float a0 = 0, a1 = 0;
                #pragma unroll
                for (int k2 = 0; k2 < 16; k2++) {
                    float2 cv = Cr[k2];
                    float2 y0 = *(const float2*)(Ac + (2 * k2) * MA + j0);
                    float2 y1 = *(const float2*)(Ac + (2 * k2 + 1) * MA + j0);
                    a0 += cv.x * y0.x + cv.y * y1.x;
                    a1 += cv.x * y0.y + cv.y * y1.y;
                }
                *(float2*)(sV + i * MA + j0) = make_float2(a0, a1);
                if (id < 32) {
                    const float2* Ar = (const float2*)(Ac + id * MA);
                    float s = 0.f;
                    #pragma unroll
                    for (int j = 0; j < 16; j++) {
                        float2 a = Ar[j];
                        s += a.x * smu[2 * j] + a.y * smu[2 * j + 1];
                    }
                    const float2* Br = (const float2*)(Bc + id * M);
                    #pragma unroll
                    for (int j = 0; j < 4; j++) {
                        float2 bb = Br[j];
                        s += bb.x * uc[2 * j] + bb.y * uc[2 * j + 1];
                    }
                    smup[id] = s;
                    g_mup[bt * N + id] = s;
                }
            }
            __syncthreads();

            // ===== R1: Sig_p = AS*A^T + Q (2x2) | Z = V*Sig (1x2) ==========
            if (tid < 256) {
                const int r0 = (tid >> 4) * 2, c0 = (tid & 15) * 2;
                const float2* Xr0 = (const float2*)(sAS + r0 * MA);
                const float2* Xr1 = (const float2*)(sAS + (r0 + 1) * MA);
                const float2* Yc0 = (const float2*)(Ac + c0 * MA);
                const float2* Yc1 = (const float2*)(Ac + (c0 + 1) * MA);
                float a00 = (r0 == c0) ? 0.01f : 0.f, a01 = 0, a10 = 0;
                float a11 = (r0 == c0) ? 0.01f : 0.f;
                #pragma unroll
                for (int k2 = 0; k2 < 16; k2++) {
                    float2 x0 = Xr0[k2], x1 = Xr1[k2], y0 = Yc0[k2], y1 = Yc1[k2];
                    a00 += x0.x * y0.x + x0.y * y0.y;  a01 += x0.x * y1.x + x0.y * y1.y;
                    a10 += x1.x * y0.x + x1.y * y0.y;  a11 += x1.x * y1.x + x1.y * y1.y;
                }
                *(float2*)(sSigp + r0 * MA + c0) = make_float2(a00, a01);
                *(float2*)(sSigp + (r0 + 1) * MA + c0) = make_float2(a10, a11);
            } else {
                const int id = tid - 256;
                const int i = id >> 4, j0 = (id & 15) * 2;
                const float2* Vr = (const float2*)(sV + i * MA);
                float a0 = 0, a1 = 0;
                #pragma unroll
                for (int k2 = 0; k2 < 16; k2++) {
                    float2 v = Vr[k2];
                    float2 y0 = *(const float2*)(sSig + (2 * k2) * MA + j0);
                    float2 y1 = *(const float2*)(sSig + (2 * k2 + 1) * MA + j0);
                    a0 += v.x * y0.x + v.y * y1.x;
                    a1 += v.x * y0.y + v.y * y1.y;
                }
                *(float2*)(sZ + i * MA + j0) = make_float2(a0, a1);
            }
            __syncthreads();

            // ===== R2: CSp | S | resid | STG Sig_p =========================
            if (tid < 256) {
                const int i = tid >> 4, j0 = (tid & 15) * 2;
                const float2* Zr = (const float2*)(sZ + i * MA);
                const float2* Aj0 = (const float2*)(Ac + j0 * MA);
                const float2* Aj1 = (const float2*)(Ac + (j0 + 1) * MA);
                float2 cv = *(const float2*)(Cc + i * MA + j0);
                float a0 = 0.01f * cv.x, a1 = 0.01f * cv.y;
                #pragma unroll
                for (int k2 = 0; k2 < 16; k2++) {
                    float2 z = Zr[k2], y0 = Aj0[k2], y1 = Aj1[k2];
                    a0 += z.x * y0.x + z.y * y0.y;
                    a1 += z.x * y1.x + z.y * y1.y;
                }
                *(float2*)(sCSp + i * MA + j0) = make_float2(a0, a1);
            } else if (tid < 384) {
                const int id = tid - 256;
                const int i = id >> 3, j0 = (id & 7) * 2;
                const float2* Zr = (const float2*)(sZ + i * MA);
                const float2* Ci = (const float2*)(Cc + i * MA);
                const float2* Vj0 = (const float2*)(sV + j0 * MA);
                const float2* Vj1 = (const float2*)(sV + (j0 + 1) * MA);
                const float2* Cj0 = (const float2*)(Cc + j0 * MA);
                const float2* Cj1 = (const float2*)(Cc + (j0 + 1) * MA);
                float a0 = (i == j0) ? 0.01f : 0.f;
                float a1 = (i == j0 + 1) ? 0.01f : 0.f;
                #pragma unroll
                for (int k2 = 0; k2 < 16; k2++) {
                    float2 z = Zr[k2], ci = Ci[k2];
                    float2 v0 = Vj0[k2], v1 = Vj1[k2];
                    float2 c0v = Cj0[k2], c1v = Cj1[k2];
                    a0 += z.x * v0.x + z.y * v0.y + 0.01f * (ci.x * c0v.x + ci.y * c0v.y);
                    a1 += z.x * v1.x + z.y * v1.y + 0.01f * (ci.x * c1v.x + ci.y * c1v.y);
                }
                *(float2*)(sS + i * 18 + j0) = make_float2(a0, a1);
            } else if (tid < 400) {
                const int i = tid - 384;
                const float2* Cr = (const float2*)(Cc + i * MA);
                float s = yc[i];
                #pragma unroll
                for (int j = 0; j < 16; j++) {
                    float2 cv = Cr[j];
                    s -= cv.x * smup[2 * j] + cv.y * smup[2 * j + 1];
                }
                sd[i] = s;
            } else {
                float2* gp = (float2*)(g_Sigp + (bt << 10));
                for (int i2 = tid - 400; i2 < 512; i2 += 112) {
                    int rr = i2 >> 4, c2 = i2 & 15;
                    gp[i2] = *(const float2*)(sSigp + rr * MA + 2 * c2);
                }
            }
            __syncthreads();

            // ===== R3: warp0 solve | others prefetch t+1 ===================
            if (tid < 32) {
                const int c = tid;
                float Sc[P], Rc[P], piv[P];
                #pragma unroll
                for (int rr = 0; rr < P; rr++) {
                    Sc[rr] = sS[rr * 18 + (c & 15)];
                    Rc[rr] = sCSp[rr * MA + c];
                }
                #pragma unroll
                for (int j = 0; j < P; j++) {
                    float f[P];
                    #pragma unroll
                    for (int rr = 0; rr < P; rr++) f[rr] = __shfl_sync(0xffffffffu, Sc[rr], j);
                    float pinv = 1.0f / f[j];
                    piv[j] = f[j];
                    float sj = Sc[j] * pinv, rj = Rc[j] * pinv;
                    #pragma unroll
                    for (int rr = 0; rr < P; rr++) {
                        if (rr != j) { Sc[rr] -= f[rr] * sj; Rc[rr] -= f[rr] * rj; }
                    }
                }
                #pragma unroll
                for (int rr = 0; rr < P; rr++) sX[rr * MA + c] = Rc[rr] / piv[rr];
            } else if (t + 1 < T) {
                const int pt = tid - 32;
                const size_t bt1 = bt + 1;
                float* An_s = sA0 + nxt * NMA;
                float* Cn_s = sC0 + nxt * (P * MA);
                float* Bn_s = sB0 + nxt * (N * M);
                const float2* An = (const float2*)(A + bt1 * (N * N));
                const float2* Cn = (const float2*)(C + bt1 * (P * N));
                const float2* Bn = (const float2*)(Bm + bt1 * (N * M));
                for (int i2 = pt; i2 < 512; i2 += 480) {
                    int rr = i2 >> 4, c2 = i2 & 15;
                    *(float2*)(An_s + rr * MA + 2 * c2) = An[i2];
                }
                if (pt < 256) {
                    int rr = pt >> 4, c2 = pt & 15;
                    *(float2*)(Cn_s + rr * MA + 2 * c2) = Cn[pt];
                }
                if (pt < 128) ((float2*)Bn_s)[pt] = Bn[pt];
                if (pt < P) syv[nxt * P + pt] = Y[bt1 * P + pt];
                else if (pt < P + M) suv[nxt * M + (pt - P)] = U[bt1 * M + (pt - P)];
            }
            __syncthreads();

            // ===== R4: Sf (fused sym) | mu_f ===============================
            if (tid < 256) {
                const int r0 = (tid >> 4) * 2, c0 = (tid & 15) * 2;
                float2 p0 = *(const float2*)(sSigp + r0 * MA + c0);
                float2 p1 = *(const float2*)(sSigp + (r0 + 1) * MA + c0);
                float m00 = 0, m01 = 0, m10 = 0, m11 = 0;
                #pragma unroll
                for (int j = 0; j < P; j++) {
                    float2 xr = *(const float2*)(sX + j * MA + r0);
                    float2 zr = *(const float2*)(sCSp + j * MA + r0);
                    float2 xc = *(const float2*)(sX + j * MA + c0);
                    float2 zc = *(const float2*)(sCSp + j * MA + c0);
                    m00 += xr.x * zc.x + zr.x * xc.x;
                    m01 += xr.x * zc.y + zr.x * xc.y;
                    m10 += xr.y * zc.x + zr.y * xc.x;
                    m11 += xr.y * zc.y + zr.y * xc.y;
                }
                float v00 = p0.x - 0.5f * m00, v01 = p0.y - 0.5f * m01;
                float v10 = p1.x - 0.5f * m10, v11 = p1.y - 0.5f * m11;
                *(float2*)(sSig + r0 * MA + c0) = make_float2(v00, v01);
                *(float2*)(sSig + (r0 + 1) * MA + c0) = make_float2(v10, v11);
                float* gf = g_Sigf + (bt << 10);
                *(float2*)(gf + r0 * 32 + c0) = make_float2(v00, v01);
                *(float2*)(gf + (r0 + 1) * 32 + c0) = make_float2(v10, v11);
            } else if (tid < 288) {
                const int i = tid - 256;
                float s = smup[i];
                #pragma unroll
                for (int j = 0; j < P; j++) s += sX[j * MA + i] * sd[j];
                smu[i] = s;
                g_muf[bt * N + i] = s;
            }
            __syncthreads();

            // ---- publish progress: all step-t stores globally visible ----
            __threadfence();
            __syncthreads();
            if (tid == 0) g_prog[b] = t + 1;
        }
    } else {
        // ============================ WORKER ROLE ========================
        const int w = blockIdx.x - 64;   // 0..83
        float* wA  = sm;
        float* wSf = sm + NMA;
        float* wSp = sm + 2 * NMA;
        float* wG  = sm + 3 * NMA;
        float* wXs = sm + 4 * NMA;
        float* wmf = sm + 5 * NMA;
        float* wmp = sm + 5 * NMA + 32;

        for (int id = w; id < 64 * (T - 1); id += 84) {
            const int t = id >> 6;
            const int b2 = id & 63;
            const size_t bt = (size_t)b2 * T + t;

            if (tid == 0) {
                while (g_prog[b2] < t + 2) { __nanosleep(200); }
            }
            __syncthreads();
            __threadfence();

            // load A, Sigf[t], Sigp[t+1], muf[t], mup[t+1]
            {
                const float2* Ab = (const float2*)(A + bt * (N * N));
                const float2* gf = (const float2*)(g_Sigf + (bt << 10));
                const float2* gp = (const float2*)(g_Sigp + ((bt + 1) << 10));
                int r = tid >> 4, c = (tid & 15) * 2;
                *(float2*)(wA + r * MA + c) = Ab[tid];
                *(float2*)(wSf + r * MA + c) = gf[tid];
                *(float2*)(wSp + r * MA + c) = gp[tid];
                if (tid < N) {
                    wmf[tid] = g_muf[bt * N + tid];
                    wmp[tid] = g_mup[(bt + 1) * N + tid];
                }
            }
            __syncthreads();

            // G = A * Sf (256 2x2 tiles)
            if (tid < 256) {
                const int r0 = (tid >> 4) * 2, c0 = (tid & 15) * 2;
                const float2* Xr0 = (const float2*)(wA + r0 * MA);
                const float2* Xr1 = (const float2*)(wA + (r0 + 1) * MA);
                float a00 = 0, a01 = 0, a10 = 0, a11 = 0;
                #pragma unroll
                for (int k2 = 0; k2 < 16; k2++) {
                    float2 x0 = Xr0[k2], x1 = Xr1[k2];
                    float2 y0 = *(const float2*)(wSf + (2 * k2) * MA + c0);
                    float2 y1 = *(const float2*)(wSf + (2 * k2 + 1) * MA + c0);
                    a00 += x0.x * y0.x + x0.y * y1.x;  a01 += x0.x * y0.y + x0.y * y1.y;
                    a10 += x1.x * y0.x + x1.y * y1.x;  a11 += x1.x * y0.y + x1.y * y1.y;
                }
                *(float2*)(wG + r0 * MA + c0) = make_float2(a00, a01);
                *(float2*)(wG + (r0 + 1) * MA + c0) = make_float2(a10, a11);
            }
            __syncthreads();

            // warp0 register GJ: Sp X = G
            if (tid < 32) {
                const int c = tid;
                float Sc[N], Gc[N];
                #pragma unroll
                for (int rr = 0; rr < N; rr++) {
                    Sc[rr] = wSp[rr * MA + c];
                    Gc[rr] = wG[rr * MA + c];
                }
                #pragma unroll
                for (int j = 0; j < N; j++) {
                    float fj = __shfl_sync(0xffffffffu, Sc[j], j);
                    float pinv = 1.0f / fj;
                    Sc[j] *= pinv; Gc[j] *= pinv;
                    float scj = Sc[j], gcj = Gc[j];
                    #pragma unroll
                    for (int rr = 0; rr < N; rr++) {
                        if (rr != j) {
                            float f = __shfl_sync(0xffffffffu, Sc[rr], j);
                            Sc[rr] -= f * scj; Gc[rr] -= f * gcj;
                        }
                    }
                }
                #pragma unroll
                for (int rr = 0; rr < N; rr++) wXs[rr * MA + c] = Gc[rr];
            }
            __syncthreads();

            // outputs
            const size_t jidx = (size_t)b2 * (T - 1) + t;
            if (tid < N) {
                float s = wmf[tid];
                #pragma unroll
                for (int kk = 0; kk < N; kk++) s -= wXs[kk * MA + tid] * wmp[kk];
                g_c[jidx * N + tid] = s;
            }
            {
                float2* gj = (float2*)(g_J + jidx * (N * N));
                int r = tid >> 4, c = (tid & 15) * 2;
                gj[tid] = *(const float2*)(wXs + r * MA + c);
            }
            if (tid < 256) {
                float* gm = g_M + jidx * (N * N);
                const int r0 = (tid >> 4) * 2, c0 = (tid & 15) * 2;
                float2 f0 = *(const float2*)(wSf + r0 * MA + c0);
                float2 f1 = *(const float2*)(wSf + (r0 + 1) * MA + c0);
                float a00 = f0.x, a01 = f0.y, a10 = f1.x, a11 = f1.y;
                #pragma unroll
                for (int kk = 0; kk < N; kk++) {
                    float x0 = wXs[kk * MA + r0], x1 = wXs[kk * MA + r0 + 1];
                    float2 g = *(const float2*)(wG + kk * MA + c0);
                    a00 -= x0 * g.x;  a01 -= x0 * g.y;
                    a10 -= x1 * g.x;  a11 -= x1 * g.y;
                }
                *(float2*)(gm + r0 * 32 + c0) = make_float2(a00, a01);
                *(float2*)(gm + (r0 + 1) * 32 + c0) = make_float2(a10, a11);
            }
            __syncthreads();
        }
    }
}

// =====================================================================
// Kernel 3 (Phase A): compose chunk operators. grid (16, 64), 256 thr.
// (verbatim 997.3 configuration)
// =====================================================================
__global__ __launch_bounds__(256) void k_scanA()
{
    const int k = blockIdx.x, b = blockIdx.y;
    const int t_lo = CHS * k;
    const int t_hi = (k == NCH - 1) ? (T - 2) : (CHS * k + CHS - 1);
    const int tid = threadIdx.x;

    __shared__ __align__(16) float sXO[NMA], sMO[NMA];
    __shared__ __align__(16) float sXt[2][NMA], sMt[2][NMA];
    __shared__ __align__(16) float sW[NMA], sXN[NMA];
    __shared__ float scO[N], sct[2][N], scN[N];

    const int r0 = (tid >> 4) * 2, c0 = (tid & 15) * 2;
    const int ra = tid >> 4, ca = (tid & 15) * 2;
    const int rb = ra + 16;

    {
        const size_t base = (size_t)b * (T - 1) + t_hi;
        const float2* gx = (const float2*)(g_J + base * (N * N));
        const float2* gm = (const float2*)(g_M + base * (N * N));
        for (int i2 = tid; i2 < 512; i2 += 256) {
            int r = i2 >> 4, c = (i2 & 15) * 2;
            *(float2*)(sXO + r * MA + c) = gx[i2];
            *(float2*)(sMO + r * MA + c) = gm[i2];
        }
        if (tid < N) scO[tid] = g_c[base * N + tid];
    }

    float2 pX0, pX1, pM0, pM1;
    float pc = 0.f;
    if (t_hi - 1 >= t_lo) {
        const size_t base = (size_t)b * (T - 1) + (t_hi - 1);
        const float2* gx = (const float2*)(g_J + base * (N * N));
        const float2* gm = (const float2*)(g_M + base * (N * N));
        pX0 = gx[tid];  pX1 = gx[tid + 256];
        pM0 = gm[tid];  pM1 = gm[tid + 256];
        if (tid < N) pc = g_c[base * N + tid];
    }
    __syncthreads();

    for (int t = t_hi - 1; t >= t_lo; t--) {
        const int buf = (t_hi - 1 - t) & 1;
        *(float2*)(sXt[buf] + ra * MA + ca) = pX0;
        *(float2*)(sXt[buf] + rb * MA + ca) = pX1;
        *(float2*)(sMt[buf] + ra * MA + ca) = pM0;
        *(float2*)(sMt[buf] + rb * MA + ca) = pM1;
        if (tid < N) sct[buf][tid] = pc;
        if (t > t_lo) {
            const size_t base = (size_t)b * (T - 1) + (t - 1);
            const float2* gx = (const float2*)(g_J + base * (N * N));
            const float2* gm = (const float2*)(g_M + base * (N * N));
            pX0 = gx[tid];  pX1 = gx[tid + 256];
            pM0 = gm[tid];  pM1 = gm[tid + 256];
            if (tid < N) pc = g_c[base * N + tid];
        }
        __syncthreads();

        const float* Xt = sXt[buf];
        const float* Mt = sMt[buf];

        {
            const float2* Mr0 = (const float2*)(sMO + r0 * MA);
            const float2* Mr1 = (const float2*)(sMO + (r0 + 1) * MA);
            const float2* Or0 = (const float2*)(sXO + r0 * MA);
            const float2* Or1 = (const float2*)(sXO + (r0 + 1) * MA);
            float w00 = 0, w01 = 0, w10 = 0, w11 = 0;
            float x00 = 0, x01 = 0, x10 = 0, x11 = 0;
            #pragma unroll
            for (int k2 = 0; k2 < 16; k2++) {
                float2 y0 = *(const float2*)(Xt + (2 * k2) * MA + c0);
                float2 y1 = *(const float2*)(Xt + (2 * k2 + 1) * MA + c0);
                float2 m0 = Mr0[k2], m1 = Mr1[k2];
                float2 o0 = Or0[k2], o1 = Or1[k2];
                w00 += m0.x * y0.x + m0.y * y1.x;  w01 += m0.x * y0.y + m0.y * y1.y;
                w10 += m1.x * y0.x + m1.y * y1.x;  w11 += m1.x * y0.y + m1.y * y1.y;
                x00 += o0.x * y0.x + o0.y * y1.x;  x01 += o0.x * y0.y + o0.y * y1.y;
                x10 += o1.x * y0.x + o1.y * y1.x;  x11 += o1.x * y0.y + o1.y * y1.y;
            }
            *(float2*)(sW + r0 * MA + c0) = make_float2(w00, w01);
            *(float2*)(sW + (r0 + 1) * MA + c0) = make_float2(w10, w11);
            *(float2*)(sXN + r0 * MA + c0) = make_float2(x00, x01);
            *(float2*)(sXN + (r0 + 1) * MA + c0) = make_float2(x10, x11);
        }
        if (tid < N) {
            float s = sct[buf][tid];
            #pragma unroll
            for (int j = 0; j < N; j++) s += Xt[j * MA + tid] * scO[j];
            scN[tid] = s;
        }
        __syncthreads();

        {
            float2 f0 = *(const float2*)(Mt + r0 * MA + c0);
            float2 f1 = *(const float2*)(Mt + (r0 + 1) * MA + c0);
            float a00 = f0.x, a01 = f0.y, a10 = f1.x, a11 = f1.y;
            #pragma unroll
            for (int j = 0; j < N; j++) {
                float2 xj = *(const float2*)(Xt + j * MA + r0);
                float2 wj = *(const float2*)(sW + j * MA + c0);
                a00 += xj.x * wj.x;  a01 += xj.x * wj.y;
                a10 += xj.y * wj.x;  a11 += xj.y * wj.y;
            }
            *(float2*)(sMO + r0 * MA + c0) = make_float2(a00, a01);
            *(float2*)(sMO + (r0 + 1) * MA + c0) = make_float2(a10, a11);
            *(float2*)(sXO + r0 * MA + c0) = *(const float2*)(sXN + r0 * MA + c0);
            *(float2*)(sXO + (r0 + 1) * MA + c0) = *(const float2*)(sXN + (r0 + 1) * MA + c0);
        }
        if (tid < N) scO[tid] = scN[tid];
        __syncthreads();
    }

    {
        const size_t obase = (size_t)b * NCH + k;
        float2* gx = (float2*)(g_OX + obase * (N * N));
        float2* gm = (float2*)(g_OM + obase * (N * N));
        for (int i2 = tid; i2 < 512; i2 += 256) {
            int r = i2 >> 4, c = (i2 & 15) * 2;
            gx[i2] = *(const float2*)(sXO + r * MA + c);
            gm[i2] = *(const float2*)(sMO + r * MA + c);
        }
        if (tid < N) g_Oc[obase * N + tid] = scO[tid];
    }
}

// =====================================================================
// Kernel 4 (Phase B): boundary states per batch. grid 64, 256 thr.
// =====================================================================
__global__ __launch_bounds__(256) void k_scanB(float* __restrict__ out)
{
    const int b = blockIdx.x;
    const int tid = threadIdx.x;

    __shared__ __align__(16) float sS[NMA], sX[NMA], sMm[NMA], sW[NMA];
    __shared__ float smu[N], smuN[N], sc[N];

    const int r0 = (tid >> 4) * 2, c0 = (tid & 15) * 2;

    {
        const size_t btL = (size_t)b * T + (T - 1);
        const float2* gf = (const float2*)(g_Sigf + (btL << 10));
        float2* ge = (float2*)(g_eS + ((size_t)b * NCH + (NCH - 1)) * (N * N));
        for (int i2 = tid; i2 < 512; i2 += 256) {
            int r = i2 >> 4, c = (i2 & 15) * 2;
            float2 v = gf[i2];
            *(float2*)(sS + r * MA + c) = v;
            ge[i2] = v;
            float* o = out + (btL * N + r) * (N + 1) + 1 + c;
            o[0] = v.x; o[1] = v.y;
        }
        if (tid < N) {
            float v = g_muf[btL * N + tid];
            smu[tid] = v;
            g_emu[((size_t)b * NCH + (NCH - 1)) * N + tid] = v;
            out[(btL * N + tid) * (N + 1)] = v;
        }
    }
    __syncthreads();

    for (int k = NCH - 2; k >= 0; k--) {
        const size_t obase = (size_t)b * NCH + (k + 1);
        {
            const float2* gx = (const float2*)(g_OX + obase * (N * N));
            const float2* gm = (const float2*)(g_OM + obase * (N * N));
            for (int i2 = tid; i2 < 512; i2 += 256) {
                int r = i2 >> 4, c = (i2 & 15) * 2;
                *(float2*)(sX + r * MA + c) = gx[i2];
                *(float2*)(sMm + r * MA + c) = gm[i2];
            }
            if (tid < N) sc[tid] = g_Oc[obase * N + tid];
        }
        __syncthreads();

        {
            const float2* Sr0 = (const float2*)(sS + r0 * MA);
            const float2* Sr1 = (const float2*)(sS + (r0 + 1) * MA);
            float a00 = 0, a01 = 0, a10 = 0, a11 = 0;
            #pragma unroll
            for (int k2 = 0; k2 < 16; k2++) {
                float2 x0 = Sr0[k2], x1 = Sr1[k2];
                float2 y0 = *(const float2*)(sX + (2 * k2) * MA + c0);
                float2 y1 = *(const float2*)(sX + (2 * k2 + 1) * MA + c0);
                a00 += x0.x * y0.x + x0.y * y1.x;  a01 += x0.x * y0.y + x0.y * y1.y;
                a10 += x1.x * y0.x + x1.y * y1.x;  a11 += x1.x * y0.y + x1.y * y1.y;
            }
            *(float2*)(sW + r0 * MA + c0) = make_float2(a00, a01);
            *(float2*)(sW + (r0 + 1) * MA + c0) = make_float2(a10, a11);
        }
        if (tid < N) {
            float s = sc[tid];
            #pragma unroll
            for (int j = 0; j < N; j++) s += sX[j * MA + tid] * smu[j];
            smuN[tid] = s;
        }
        __syncthreads();

        {
            float2 f0 = *(const float2*)(sMm + r0 * MA + c0);
            float2 f1 = *(const float2*)(sMm + (r0 + 1) * MA + c0);
            float a00 = f0.x, a01 = f0.y, a10 = f1.x, a11 = f1.y;
            #pragma unroll
            for (int j = 0; j < N; j++) {
                float2 xj = *(const float2*)(sX + j * MA + r0);
                float2 wj = *(const float2*)(sW + j * MA + c0);
                a00 += xj.x * wj.x;  a01 += xj.x * wj.y;
                a10 += xj.y * wj.x;  a11 += xj.y * wj.y;
            }
            *(float2*)(sS + r0 * MA + c0) = make_float2(a00, a01);
            *(float2*)(sS + (r0 + 1) * MA + c0) = make_float2(a10, a11);
            float* ge = g_eS + ((size_t)b * NCH + k) * (N * N);
            *(float2*)(ge + r0 * 32 + c0) = make_float2(a00, a01);
            *(float2*)(ge + (r0 + 1) * 32 + c0) = make_float2(a10, a11);
        }
        if (tid < N) {
            smu[tid] = smuN[tid];
            g_emu[((size_t)b * NCH + k) * N + tid] = smuN[tid];
        }
        __syncthreads();
    }
}

// =====================================================================
// Kernel 5 (Phase C): per-chunk backward recursion. grid (16, 64), 256 thr.
// =====================================================================
__global__ __launch_bounds__(256) void k_scanC(float* __restrict__ out)
{
    const int k = blockIdx.x, b = blockIdx.y;
    const int t_lo = CHS * k;
    const int t_hi = (k == NCH - 1) ? (T - 2) : (CHS * k + CHS - 1);
    const int tid = threadIdx.x;

    __shared__ __align__(16) float sS[NMA], sW[NMA];
    __shared__ __align__(16) float sX[2][NMA], sMm[2][NMA];
    __shared__ float smu[N], smuN[N], sc[2][N];

    const int r0 = (tid >> 4) * 2, c0 = (tid & 15) * 2;
    const int ra = tid >> 4, ca = (tid & 15) * 2;
    const int rb = ra + 16;

    {
        const size_t ebase = (size_t)b * NCH + k;
        const float2* ge = (const float2*)(g_eS + ebase * (N * N));
        for (int i2 = tid; i2 < 512; i2 += 256) {
            int r = i2 >> 4, c = (i2 & 15) * 2;
            *(float2*)(sS + r * MA + c) = ge[i2];
        }
        if (tid < N) smu[tid] = g_emu[ebase * N + tid];
    }

    float2 pX0, pX1, pM0, pM1;
    float pc = 0.f;
    {
        const size_t base = (size_t)b * (T - 1) + t_hi;
        const float2* gx = (const float2*)(g_J + base * (N * N));
        const float2* gm = (const float2*)(g_M + base * (N * N));
        pX0 = gx[tid];  pX1 = gx[tid + 256];
        pM0 = gm[tid];  pM1 = gm[tid + 256];
        if (tid < N) pc = g_c[base * N + tid];
    }
    __syncthreads();

    for (int t = t_hi; t >= t_lo; t--) {
        const int buf = (t_hi - t) & 1;
        const size_t bt = (size_t)b * T + t;
        *(float2*)(sX[buf] + ra * MA + ca) = pX0;
        *(float2*)(sX[buf] + rb * MA + ca) = pX1;
        *(float2*)(sMm[buf] + ra * MA + ca) = pM0;
        *(float2*)(sMm[buf] + rb * MA + ca) = pM1;
        if (tid < N) sc[buf][tid] = pc;
        if (t > t_lo) {
            const size_t base = (size_t)b * (T - 1) + (t - 1);
            const float2* gx = (const float2*)(g_J + base * (N * N));
            const float2* gm = (const float2*)(g_M + base * (N * N));
            pX0 = gx[tid];  pX1 = gx[tid + 256];
            pM0 = gm[tid];  pM1 = gm[tid + 256];
            if (tid < N) pc = g_c[base * N + tid];
        }
        __syncthreads();

        const float* Xb = sX[buf];
        const float* Mb = sMm[buf];

        {
            const float2* Sr0 = (const float2*)(sS + r0 * MA);
            const float2* Sr1 = (const float2*)(sS + (r0 + 1) * MA);
            float a00 = 0, a01 = 0, a10 = 0, a11 = 0;
            #pragma unroll
            for (int k2 = 0; k2 < 16; k2++) {
                float2 x0 = Sr0[k2], x1 = Sr1[k2];
                float2 y0 = *(const float2*)(Xb + (2 * k2) * MA + c0);
                float2 y1 = *(const float2*)(Xb + (2 * k2 + 1) * MA + c0);
                a00 += x0.x * y0.x + x0.y * y1.x;  a01 += x0.x * y0.y + x0.y * y1.y;
                a10 += x1.x * y0.x + x1.y * y1.x;  a11 += x1.x * y0.y + x1.y * y1.y;
            }
            *(float2*)(sW + r0 * MA + c0) = make_float2(a00, a01);
            *(float2*)(sW + (r0 + 1) * MA + c0) = make_float2(a10, a11);
        }
        if (tid < N) {
            float s = sc[buf][tid];
            #pragma unroll
            for (int j = 0; j < N; j++) s += Xb[j * MA + tid] * smu[j];
            smuN[tid] = s;
        }
        __syncthreads();

        {
            float2 f0 = *(const float2*)(Mb + r0 * MA + c0);
            float2 f1 = *(const float2*)(Mb + (r0 + 1) * MA + c0);
            float a00 = f0.x, a01 = f0.y, a10 = f1.x, a11 = f1.y;
            #pragma unroll
            for (int j = 0; j < N; j++) {
                float2 xj = *(const float2*)(Xb + j * MA + r0);
                float2 wj = *(const float2*)(sW + j * MA + c0);
                a00 += xj.x * wj.x;  a01 += xj.x * wj.y;
                a10 += xj.y * wj.x;  a11 += xj.y * wj.y;
            }
            *(float2*)(sS + r0 * MA + c0) = make_float2(a00, a01);
            *(float2*)(sS + (r0 + 1) * MA + c0) = make_float2(a10, a11);
            float* o = out + (bt * N + r0) * (N + 1) + 1 + c0;
            o[0] = a00; o[1] = a01;
            o[N + 1] = a10; o[N + 2] = a11;
        }
        if (tid < N) {
            smu[tid] = smuN[tid];
            out[(bt * N + tid) * (N + 1)] = smuN[tid];
        }
        __syncthreads();
    }
}

extern "C" void kernel_launch(void* const* d_in, const int* in_sizes, int n_in,
                              void* d_out, int out_size) {
    (void)in_sizes; (void)n_in; (void)out_size;
    const float* Y   = (const float*)d_in[0];
    const float* U   = (const float*)d_in[1];
    const float* A   = (const float*)d_in[2];
    const float* Bm  = (const float*)d_in[3];
    const float* C   = (const float*)d_in[4];
    const float* mu0 = (const float*)d_in[5];
    const float* S0  = (const float*)d_in[6];
    float* out = (float*)d_out;

    k_main<<<148, 512>>>(Y, U, A, Bm, C, mu0, S0);
    k_scanA<<<dim3(NCH, BATCH), 256>>>();
    k_scanB<<<BATCH, 256>>>(out);
    k_scanC<<<dim3(NCH, BATCH), 256>>>(out);
}

// round 17
// speedup vs baseline: 1.0453x; 1.0453x over previous
#include <cuda_runtime.h>

#define BATCH 64
#define T 128
#define N 32
#define M 8
#define P 16
#define MA 34    // padded row stride (even -> float2-aligned rows)
#define NCH 16   // backward-scan chunks
#define CHS 8    // chunk size
#define NMA (N * MA)

// Global scratch
__device__ float g_muf[BATCH * T * N];
__device__ float g_mup[BATCH * T * N];
__device__ float g_Sigf[(size_t)BATCH * T * N * N];
__device__ float g_Sigp[(size_t)BATCH * T * N * N];
__device__ float g_J[(size_t)BATCH * (T - 1) * N * N];   // X_t = J_t^T
__device__ float g_M[(size_t)BATCH * (T - 1) * N * N];   // M_t
__device__ float g_c[(size_t)BATCH * (T - 1) * N];       // c_t
__device__ float g_OX[(size_t)BATCH * NCH * N * N];
__device__ float g_OM[(size_t)BATCH * NCH * N * N];
__device__ float g_Oc[(size_t)BATCH * NCH * N];
__device__ float g_eS[(size_t)BATCH * NCH * N * N];
__device__ float g_emu[(size_t)BATCH * NCH * N];
__device__ volatile int g_prog[BATCH];   // forward progress flags

// =====================================================================
// k_main: grid 148, 512 thr, 1 block/SM (one resident wave).
//   blocks 0..63  : forward Kalman filter + progress flags (every 4 steps)
//   blocks 64..147: J2 workers consuming (b,t) tasks as they become ready
// =====================================================================
__global__ __launch_bounds__(512, 1) void k_main(
    const float* __restrict__ Y, const float* __restrict__ U,
    const float* __restrict__ A, const float* __restrict__ Bm,
    const float* __restrict__ C, const float* __restrict__ mu0,
    const float* __restrict__ Sig0)
{
    __shared__ __align__(16) float sm[9632];
    const int tid = threadIdx.x;

    if (blockIdx.x < 64) {
        // ============================ FORWARD ROLE =======================
        const int b = blockIdx.x;
        float* sA0  = sm;            // [2][NMA]
        float* sC0  = sm + 2176;     // [2][P*MA]
        float* sB0  = sm + 3264;     // [2][N*M]
        float* sV   = sm + 3776;
        float* sZ   = sm + 4320;
        float* sCSp = sm + 4864;
        float* sSig = sm + 5408;
        float* sAS  = sm + 6496;
        float* sSigp= sm + 7584;
        float* sS   = sm + 8672;     // stride 18
        float* sX   = sm + 8960;
        float* syv  = sm + 9504;     // [2][P]
        float* suv  = sm + 9536;     // [2][M]
        float* smu  = sm + 9552;
        float* smup = sm + 9584;
        float* sd   = sm + 9616;

        // ---- init state + t=0 inputs ----
        if (tid < N) smu[tid] = mu0[tid];
        {
            int r = tid >> 4, c2 = tid & 15;
            *(float2*)(sSig + r * MA + 2 * c2) = ((const float2*)Sig0)[tid];
        }
        {
            const size_t bt = (size_t)b * T;
            const float2* Ab = (const float2*)(A + bt * (N * N));
            const float2* Cb = (const float2*)(C + bt * (P * N));
            const float2* Bb = (const float2*)(Bm + bt * (N * M));
            {
                int r = tid >> 4, c2 = tid & 15;
                *(float2*)(sA0 + r * MA + 2 * c2) = Ab[tid];
            }
            if (tid < 256) {
                int r = tid >> 4, c2 = tid & 15;
                *(float2*)(sC0 + r * MA + 2 * c2) = Cb[tid];
            }
            if (tid < 128) ((float2*)sB0)[tid] = Bb[tid];
            if (tid < P) syv[tid] = Y[bt * P + tid];
            if (tid < M) suv[tid] = U[bt * M + tid];
        }
        __syncthreads();

        for (int t = 0; t < T; t++) {
            const int cur = t & 1, nxt = cur ^ 1;
            const size_t bt = (size_t)b * T + t;
            const float* Ac = sA0 + cur * NMA;
            const float* Cc = sC0 + cur * (P * MA);
            const float* Bc = sB0 + cur * (N * M);
            const float* yc = syv + cur * P;
            const float* uc = suv + cur * M;

            // ===== R0: AS = A*Sig (2x2) | V = C*A (1x2) + mu_p =============
            if (tid < 256) {
                const int r0 = (tid >> 4) * 2, c0 = (tid & 15) * 2;
                const float2* Xr0 = (const float2*)(Ac + r0 * MA);
                const float2* Xr1 = (const float2*)(Ac + (r0 + 1) * MA);
                float a00 = 0, a01 = 0, a10 = 0, a11 = 0;
                #pragma unroll
                for (int k2 = 0; k2 < 16; k2++) {
                    float2 x0 = Xr0[k2], x1 = Xr1[k2];
                    float2 y0 = *(const float2*)(sSig + (2 * k2) * MA + c0);
                    float2 y1 = *(const float2*)(sSig + (2 * k2 + 1) * MA + c0);
                    a00 += x0.x * y0.x + x0.y * y1.x;  a01 += x0.x * y0.y + x0.y * y1.y;
                    a10 += x1.x * y0.x + x1.y * y1.x;  a11 += x1.x * y0.y + x1.y * y1.y;
                }
                *(float2*)(sAS + r0 * MA + c0) = make_float2(a00, a01);
                *(float2*)(sAS + (r0 + 1) * MA + c0) = make_float2(a10, a11);
            } else {
                const int id = tid - 256;
                const int i = id >> 4, j0 = (id & 15) * 2;
                const float2* Cr = (const float2*)(Cc + i * MA);
                float a0 = 0, a1 = 0;
                #pragma unroll
                for (int k2 = 0; k2 < 16; k2++) {
                    float2 cv = Cr[k2];
                    float2 y0 = *(const float2*)(Ac + (2 * k2) * MA + j0);
                    float2 y1 = *(const float2*)(Ac + (2 * k2 + 1) * MA + j0);
                    a0 += cv.x * y0.x + cv.y * y1.x;
                    a1 += cv.x * y0.y + cv.y * y1.y;
                }
                *(float2*)(sV + i * MA + j0) = make_float2(a0, a1);
                if (id < 32) {
                    const float2* Ar = (const float2*)(Ac + id * MA);
                    float s = 0.f;
                    #pragma unroll
                    for (int j = 0; j < 16; j++) {
                        float2 a = Ar[j];
                        s += a.x * smu[2 * j] + a.y * smu[2 * j + 1];
                    }
                    const float2* Br = (const float2*)(Bc + id * M);
                    #pragma unroll
                    for (int j = 0; j < 4; j++) {
                        float2 bb = Br[j];
                        s += bb.x * uc[2 * j] + bb.y * uc[2 * j + 1];
                    }
                    smup[id] = s;
                    g_mup[bt * N + id] = s;
                }
            }
            __syncthreads();

            // ===== R1: Sig_p = AS*A^T + Q (2x2) | Z = V*Sig (1x2) ==========
            if (tid < 256) {
                const int r0 = (tid >> 4) * 2, c0 = (tid & 15) * 2;
                const float2* Xr0 = (const float2*)(sAS + r0 * MA);
                const float2* Xr1 = (const float2*)(sAS + (r0 + 1) * MA);
                const float2* Yc0 = (const float2*)(Ac + c0 * MA);
                const float2* Yc1 = (const float2*)(Ac + (c0 + 1) * MA);
                float a00 = (r0 == c0) ? 0.01f : 0.f, a01 = 0, a10 = 0;
                float a11 = (r0 == c0) ? 0.01f : 0.f;
                #pragma unroll
                for (int k2 = 0; k2 < 16; k2++) {
                    float2 x0 = Xr0[k2], x1 = Xr1[k2], y0 = Yc0[k2], y1 = Yc1[k2];
                    a00 += x0.x * y0.x + x0.y * y0.y;  a01 += x0.x * y1.x + x0.y * y1.y;
                    a10 += x1.x * y0.x + x1.y * y0.y;  a11 += x1.x * y1.x + x1.y * y1.y;
                }
                *(float2*)(sSigp + r0 * MA + c0) = make_float2(a00, a01);
                *(float2*)(sSigp + (r0 + 1) * MA + c0) = make_float2(a10, a11);
            } else {
                const int id = tid - 256;
                const int i = id >> 4, j0 = (id & 15) * 2;
                const float2* Vr = (const float2*)(sV + i * MA);
                float a0 = 0, a1 = 0;
                #pragma unroll
                for (int k2 = 0; k2 < 16; k2++) {
                    float2 v = Vr[k2];
                    float2 y0 = *(const float2*)(sSig + (2 * k2) * MA + j0);
                    float2 y1 = *(const float2*)(sSig + (2 * k2 + 1) * MA + j0);
                    a0 += v.x * y0.x + v.y * y1.x;
                    a1 += v.x * y0.y + v.y * y1.y;
                }
                *(float2*)(sZ + i * MA + j0) = make_float2(a0, a1);
            }
            __syncthreads();

            // ===== R2: CSp | S | resid | STG Sig_p =========================
            if (tid < 256) {
                const int i = tid >> 4, j0 = (tid & 15) * 2;
                const float2* Zr = (const float2*)(sZ + i * MA);
                const float2* Aj0 = (const float2*)(Ac + j0 * MA);
                const float2* Aj1 = (const float2*)(Ac + (j0 + 1) * MA);
                float2 cv = *(const float2*)(Cc + i * MA + j0);
                float a0 = 0.01f * cv.x, a1 = 0.01f * cv.y;
                #pragma unroll
                for (int k2 = 0; k2 < 16; k2++) {
                    float2 z = Zr[k2], y0 = Aj0[k2], y1 = Aj1[k2];
                    a0 += z.x * y0.x + z.y * y0.y;
                    a1 += z.x * y1.x + z.y * y1.y;
                }
                *(float2*)(sCSp + i * MA + j0) = make_float2(a0, a1);
            } else if (tid < 384) {
                const int id = tid - 256;
                const int i = id >> 3, j0 = (id & 7) * 2;
                const float2* Zr = (const float2*)(sZ + i * MA);
                const float2* Ci = (const float2*)(Cc + i * MA);
                const float2* Vj0 = (const float2*)(sV + j0 * MA);
                const float2* Vj1 = (const float2*)(sV + (j0 + 1) * MA);
                const float2* Cj0 = (const float2*)(Cc + j0 * MA);
                const float2* Cj1 = (const float2*)(Cc + (j0 + 1) * MA);
                float a0 = (i == j0) ? 0.01f : 0.f;
                float a1 = (i == j0 + 1) ? 0.01f : 0.f;
                #pragma unroll
                for (int k2 = 0; k2 < 16; k2++) {
                    float2 z = Zr[k2], ci = Ci[k2];
                    float2 v0 = Vj0[k2], v1 = Vj1[k2];
                    float2 c0v = Cj0[k2], c1v = Cj1[k2];
                    a0 += z.x * v0.x + z.y * v0.y + 0.01f * (ci.x * c0v.x + ci.y * c0v.y);
                    a1 += z.x * v1.x + z.y * v1.y + 0.01f * (ci.x * c1v.x + ci.y * c1v.y);
                }
                *(float2*)(sS + i * 18 + j0) = make_float2(a0, a1);
            } else if (tid < 400) {
                const int i = tid - 384;
                const float2* Cr = (const float2*)(Cc + i * MA);
                float s = yc[i];
                #pragma unroll
                for (int j = 0; j < 16; j++) {
                    float2 cv = Cr[j];
                    s -= cv.x * smup[2 * j] + cv.y * smup[2 * j + 1];
                }
                sd[i] = s;
            } else {
                float2* gp = (float2*)(g_Sigp + (bt << 10));
                for (int i2 = tid - 400; i2 < 512; i2 += 112) {
                    int rr = i2 >> 4, c2 = i2 & 15;
                    gp[i2] = *(const float2*)(sSigp + rr * MA + 2 * c2);
                }
            }
            __syncthreads();

            // ===== R3: warp0 solve | others prefetch t+1 ===================
            if (tid < 32) {
                const int c = tid;
                float Sc[P], Rc[P], piv[P];
                #pragma unroll
                for (int rr = 0; rr < P; rr++) {
                    Sc[rr] = sS[rr * 18 + (c & 15)];
                    Rc[rr] = sCSp[rr * MA + c];
                }
                #pragma unroll
                for (int j = 0; j < P; j++) {
                    float f[P];
                    #pragma unroll
                    for (int rr = 0; rr < P; rr++) f[rr] = __shfl_sync(0xffffffffu, Sc[rr], j);
                    float pinv = 1.0f / f[j];
                    piv[j] = f[j];
                    float sj = Sc[j] * pinv, rj = Rc[j] * pinv;
                    #pragma unroll
                    for (int rr = 0; rr < P; rr++) {
                        if (rr != j) { Sc[rr] -= f[rr] * sj; Rc[rr] -= f[rr] * rj; }
                    }
                }
                #pragma unroll
                for (int rr = 0; rr < P; rr++) sX[rr * MA + c] = Rc[rr] / piv[rr];
            } else if (t + 1 < T) {
                const int pt = tid - 32;
                const size_t bt1 = bt + 1;
                float* An_s = sA0 + nxt * NMA;
                float* Cn_s = sC0 + nxt * (P * MA);
                float* Bn_s = sB0 + nxt * (N * M);
                const float2* An = (const float2*)(A + bt1 * (N * N));
                const float2* Cn = (const float2*)(C + bt1 * (P * N));
                const float2* Bn = (const float2*)(Bm + bt1 * (N * M));
                for (int i2 = pt; i2 < 512; i2 += 480) {
                    int rr = i2 >> 4, c2 = i2 & 15;
                    *(float2*)(An_s + rr * MA + 2 * c2) = An[i2];
                }
                if (pt < 256) {
                    int rr = pt >> 4, c2 = pt & 15;
                    *(float2*)(Cn_s + rr * MA + 2 * c2) = Cn[pt];
                }
                if (pt < 128) ((float2*)Bn_s)[pt] = Bn[pt];
                if (pt < P) syv[nxt * P + pt] = Y[bt1 * P + pt];
                else if (pt < P + M) suv[nxt * M + (pt - P)] = U[bt1 * M + (pt - P)];
            }
            __syncthreads();

            // ===== R4: Sf (fused sym) | mu_f ===============================
            if (tid < 256) {
                const int r0 = (tid >> 4) * 2, c0 = (tid & 15) * 2;
                float2 p0 = *(const float2*)(sSigp + r0 * MA + c0);
                float2 p1 = *(const float2*)(sSigp + (r0 + 1) * MA + c0);
                float m00 = 0, m01 = 0, m10 = 0, m11 = 0;
                #pragma unroll
                for (int j = 0; j < P; j++) {
                    float2 xr = *(const float2*)(sX + j * MA + r0);
                    float2 zr = *(const float2*)(sCSp + j * MA + r0);
                    float2 xc = *(const float2*)(sX + j * MA + c0);
                    float2 zc = *(const float2*)(sCSp + j * MA + c0);
                    m00 += xr.x * zc.x + zr.x * xc.x;
                    m01 += xr.x * zc.y + zr.x * xc.y;
                    m10 += xr.y * zc.x + zr.y * xc.x;
                    m11 += xr.y * zc.y + zr.y * xc.y;
                }
                float v00 = p0.x - 0.5f * m00, v01 = p0.y - 0.5f * m01;
                float v10 = p1.x - 0.5f * m10, v11 = p1.y - 0.5f * m11;
                *(float2*)(sSig + r0 * MA + c0) = make_float2(v00, v01);
                *(float2*)(sSig + (r0 + 1) * MA + c0) = make_float2(v10, v11);
                float* gf = g_Sigf + (bt << 10);
                *(float2*)(gf + r0 * 32 + c0) = make_float2(v00, v01);
                *(float2*)(gf + (r0 + 1) * 32 + c0) = make_float2(v10, v11);
            } else if (tid < 288) {
                const int i = tid - 256;
                float s = smup[i];
                #pragma unroll
                for (int j = 0; j < P; j++) s += sX[j * MA + i] * sd[j];
                smu[i] = s;
                g_muf[bt * N + i] = s;
            }
            __syncthreads();

            // ---- publish progress every 4 steps (amortized fence) ----
            if (((t + 1) & 3) == 0) {
                __threadfence();
                __syncthreads();
                if (tid == 0) g_prog[b] = t + 1;
            }
        }
    } else {
        // ============================ WORKER ROLE ========================
        const int w = blockIdx.x - 64;   // 0..83
        float* wA  = sm;
        float* wSf = sm + NMA;
        float* wSp = sm + 2 * NMA;
        float* wG  = sm + 3 * NMA;
        float* wXs = sm + 4 * NMA;
        float* wmf = sm + 5 * NMA;
        float* wmp = sm + 5 * NMA + 32;

        for (int id = w; id < 64 * (T - 1); id += 84) {
            const int t = id >> 6;
            const int b2 = id & 63;
            const size_t bt = (size_t)b2 * T + t;

            if (tid == 0) {
                while (g_prog[b2] < t + 2) { __nanosleep(200); }
            }
            __syncthreads();
            __threadfence();

            // load A, Sigf[t], Sigp[t+1], muf[t], mup[t+1]
            {
                const float2* Ab = (const float2*)(A + bt * (N * N));
                const float2* gf = (const float2*)(g_Sigf + (bt << 10));
                const float2* gp = (const float2*)(g_Sigp + ((bt + 1) << 10));
                int r = tid >> 4, c = (tid & 15) * 2;
                *(float2*)(wA + r * MA + c) = Ab[tid];
                *(float2*)(wSf + r * MA + c) = gf[tid];
                *(float2*)(wSp + r * MA + c) = gp[tid];
                if (tid < N) {
                    wmf[tid] = g_muf[bt * N + tid];
                    wmp[tid] = g_mup[(bt + 1) * N + tid];
                }
            }
            __syncthreads();

            // G = A * Sf (256 2x2 tiles)
            if (tid < 256) {
                const int r0 = (tid >> 4) * 2, c0 = (tid & 15) * 2;
                const float2* Xr0 = (const float2*)(wA + r0 * MA);
                const float2* Xr1 = (const float2*)(wA + (r0 + 1) * MA);
                float a00 = 0, a01 = 0, a10 = 0, a11 = 0;
                #pragma unroll
                for (int k2 = 0; k2 < 16; k2++) {
                    float2 x0 = Xr0[k2], x1 = Xr1[k2];
                    float2 y0 = *(const float2*)(wSf + (2 * k2) * MA + c0);
                    float2 y1 = *(const float2*)(wSf + (2 * k2 + 1) * MA + c0);
                    a00 += x0.x * y0.x + x0.y * y1.x;  a01 += x0.x * y0.y + x0.y * y1.y;
                    a10 += x1.x * y0.x + x1.y * y1.x;  a11 += x1.x * y0.y + x1.y * y1.y;
                }
                *(float2*)(wG + r0 * MA + c0) = make_float2(a00, a01);
                *(float2*)(wG + (r0 + 1) * MA + c0) = make_float2(a10, a11);
            }
            __syncthreads();

            // warp0 register GJ: Sp X = G
            if (tid < 32) {
                const int c = tid;
                float Sc[N], Gc[N];
                #pragma unroll
                for (int rr = 0; rr < N; rr++) {
                    Sc[rr] = wSp[rr * MA + c];
                    Gc[rr] = wG[rr * MA + c];
                }
                #pragma unroll
                for (int j = 0; j < N; j++) {
                    float fj = __shfl_sync(0xffffffffu, Sc[j], j);
                    float pinv = 1.0f / fj;
                    Sc[j] *= pinv; Gc[j] *= pinv;
                    float scj = Sc[j], gcj = Gc[j];
                    #pragma unroll
                    for (int rr = 0; rr < N; rr++) {
                        if (rr != j) {
                            float f = __shfl_sync(0xffffffffu, Sc[rr], j);
                            Sc[rr] -= f * scj; Gc[rr] -= f * gcj;
                        }
                    }
                }
                #pragma unroll
                for (int rr = 0; rr < N; rr++) wXs[rr * MA + c] = Gc[rr];
            }
            __syncthreads();

            // outputs
            const size_t jidx = (size_t)b2 * (T - 1) + t;
            if (tid < N) {
                float s = wmf[tid];
                #pragma unroll
                for (int kk = 0; kk < N; kk++) s -= wXs[kk * MA + tid] * wmp[kk];
                g_c[jidx * N + tid] = s;
            }
            {
                float2* gj = (float2*)(g_J + jidx * (N * N));
                int r = tid >> 4, c = (tid & 15) * 2;
                gj[tid] = *(const float2*)(wXs + r * MA + c);
            }
            if (tid < 256) {
                float* gm = g_M + jidx * (N * N);
                const int r0 = (tid >> 4) * 2, c0 = (tid & 15) * 2;
                float2 f0 = *(const float2*)(wSf + r0 * MA + c0);
                float2 f1 = *(const float2*)(wSf + (r0 + 1) * MA + c0);
                float a00 = f0.x, a01 = f0.y, a10 = f1.x, a11 = f1.y;
                #pragma unroll
                for (int kk = 0; kk < N; kk++) {
                    float x0 = wXs[kk * MA + r0], x1 = wXs[kk * MA + r0 + 1];
                    float2 g = *(const float2*)(wG + kk * MA + c0);
                    a00 -= x0 * g.x;  a01 -= x0 * g.y;
                    a10 -= x1 * g.x;  a11 -= x1 * g.y;
                }
                *(float2*)(gm + r0 * 32 + c0) = make_float2(a00, a01);
                *(float2*)(gm + (r0 + 1) * 32 + c0) = make_float2(a10, a11);
            }
            __syncthreads();
        }
    }
}

// =====================================================================
// Kernel 3 (Phase A): compose chunk operators. grid (16, 64), 256 thr.
// (verbatim 997.3 configuration)
// =====================================================================
__global__ __launch_bounds__(256) void k_scanA()
{
    const int k = blockIdx.x, b = blockIdx.y;
    const int t_lo = CHS * k;
    const int t_hi = (k == NCH - 1) ? (T - 2) : (CHS * k + CHS - 1);
    const int tid = threadIdx.x;

    __shared__ __align__(16) float sXO[NMA], sMO[NMA];
    __shared__ __align__(16) float sXt[2][NMA], sMt[2][NMA];
    __shared__ __align__(16) float sW[NMA], sXN[NMA];
    __shared__ float scO[N], sct[2][N], scN[N];

    const int r0 = (tid >> 4) * 2, c0 = (tid & 15) * 2;
    const int ra = tid >> 4, ca = (tid & 15) * 2;
    const int rb = ra + 16;

    {
        const size_t base = (size_t)b * (T - 1) + t_hi;
        const float2* gx = (const float2*)(g_J + base * (N * N));
        const float2* gm = (const float2*)(g_M + base * (N * N));
        for (int i2 = tid; i2 < 512; i2 += 256) {
            int r = i2 >> 4, c = (i2 & 15) * 2;
            *(float2*)(sXO + r * MA + c) = gx[i2];
            *(float2*)(sMO + r * MA + c) = gm[i2];
        }
        if (tid < N) scO[tid] = g_c[base * N + tid];
    }

    float2 pX0, pX1, pM0, pM1;
    float pc = 0.f;
    if (t_hi - 1 >= t_lo) {
        const size_t base = (size_t)b * (T - 1) + (t_hi - 1);
        const float2* gx = (const float2*)(g_J + base * (N * N));
        const float2* gm = (const float2*)(g_M + base * (N * N));
        pX0 = gx[tid];  pX1 = gx[tid + 256];
        pM0 = gm[tid];  pM1 = gm[tid + 256];
        if (tid < N) pc = g_c[base * N + tid];
    }
    __syncthreads();

    for (int t = t_hi - 1; t >= t_lo; t--) {
        const int buf = (t_hi - 1 - t) & 1;
        *(float2*)(sXt[buf] + ra * MA + ca) = pX0;
        *(float2*)(sXt[buf] + rb * MA + ca) = pX1;
        *(float2*)(sMt[buf] + ra * MA + ca) = pM0;
        *(float2*)(sMt[buf] + rb * MA + ca) = pM1;
        if (tid < N) sct[buf][tid] = pc;
        if (t > t_lo) {
            const size_t base = (size_t)b * (T - 1) + (t - 1);
            const float2* gx = (const float2*)(g_J + base * (N * N));
            const float2* gm = (const float2*)(g_M + base * (N * N));
            pX0 = gx[tid];  pX1 = gx[tid + 256];
            pM0 = gm[tid];  pM1 = gm[tid + 256];
            if (tid < N) pc = g_c[base * N + tid];
        }
        __syncthreads();

        const float* Xt = sXt[buf];
        const float* Mt = sMt[buf];

        {
            const float2* Mr0 = (const float2*)(sMO + r0 * MA);
            const float2* Mr1 = (const float2*)(sMO + (r0 + 1) * MA);
            const float2* Or0 = (const float2*)(sXO + r0 * MA);
            const float2* Or1 = (const float2*)(sXO + (r0 + 1) * MA);
            float w00 = 0, w01 = 0, w10 = 0, w11 = 0;
            float x00 = 0, x01 = 0, x10 = 0, x11 = 0;
            #pragma unroll
            for (int k2 = 0; k2 < 16; k2++) {
                float2 y0 = *(const float2*)(Xt + (2 * k2) * MA + c0);
                float2 y1 = *(const float2*)(Xt + (2 * k2 + 1) * MA + c0);
                float2 m0 = Mr0[k2], m1 = Mr1[k2];
                float2 o0 = Or0[k2], o1 = Or1[k2];
                w00 += m0.x * y0.x + m0.y * y1.x;  w01 += m0.x * y0.y + m0.y * y1.y;
                w10 += m1.x * y0.x + m1.y * y1.x;  w11 += m1.x * y0.y + m1.y * y1.y;
                x00 += o0.x * y0.x + o0.y * y1.x;  x01 += o0.x * y0.y + o0.y * y1.y;
                x10 += o1.x * y0.x + o1.y * y1.x;  x11 += o1.x * y0.y + o1.y * y1.y;
            }
            *(float2*)(sW + r0 * MA + c0) = make_float2(w00, w01);
            *(float2*)(sW + (r0 + 1) * MA + c0) = make_float2(w10, w11);
            *(float2*)(sXN + r0 * MA + c0) = make_float2(x00, x01);
            *(float2*)(sXN + (r0 + 1) * MA + c0) = make_float2(x10, x11);
        }
        if (tid < N) {
            float s = sct[buf][tid];
            #pragma unroll
            for (int j = 0; j < N; j++) s += Xt[j * MA + tid] * scO[j];
            scN[tid] = s;
        }
        __syncthreads();

        {
            float2 f0 = *(const float2*)(Mt + r0 * MA + c0);
            float2 f1 = *(const float2*)(Mt + (r0 + 1) * MA + c0);
            float a00 = f0.x, a01 = f0.y, a10 = f1.x, a11 = f1.y;
            #pragma unroll
            for (int j = 0; j < N; j++) {
                float2 xj = *(const float2*)(Xt + j * MA + r0);
                float2 wj = *(const float2*)(sW + j * MA + c0);
                a00 += xj.x * wj.x;  a01 += xj.x * wj.y;
                a10 += xj.y * wj.x;  a11 += xj.y * wj.y;
            }
            *(float2*)(sMO + r0 * MA + c0) = make_float2(a00, a01);
            *(float2*)(sMO + (r0 + 1) * MA + c0) = make_float2(a10, a11);
            *(float2*)(sXO + r0 * MA + c0) = *(const float2*)(sXN + r0 * MA + c0);
            *(float2*)(sXO + (r0 + 1) * MA + c0) = *(const float2*)(sXN + (r0 + 1) * MA + c0);
        }
        if (tid < N) scO[tid] = scN[tid];
        __syncthreads();
    }

    {
        const size_t obase = (size_t)b * NCH + k;
        float2* gx = (float2*)(g_OX + obase * (N * N));
        float2* gm = (float2*)(g_OM + obase * (N * N));
        for (int i2 = tid; i2 < 512; i2 += 256) {
            int r = i2 >> 4, c = (i2 & 15) * 2;
            gx[i2] = *(const float2*)(sXO + r * MA + c);
            gm[i2] = *(const float2*)(sMO + r * MA + c);
        }
        if (tid < N) g_Oc[obase * N + tid] = scO[tid];
    }
}

// =====================================================================
// Kernel 4 (Phase B): boundary states per batch. grid 64, 256 thr.
// =====================================================================
__global__ __launch_bounds__(256) void k_scanB(float* __restrict__ out)
{
    const int b = blockIdx.x;
    const int tid = threadIdx.x;

    __shared__ __align__(16) float sS[NMA], sX[NMA], sMm[NMA], sW[NMA];
    __shared__ float smu[N], smuN[N], sc[N];

    const int r0 = (tid >> 4) * 2, c0 = (tid & 15) * 2;

    {
        const size_t btL = (size_t)b * T + (T - 1);
        const float2* gf = (const float2*)(g_Sigf + (btL << 10));
        float2* ge = (float2*)(g_eS + ((size_t)b * NCH + (NCH - 1)) * (N * N));
        for (int i2 = tid; i2 < 512; i2 += 256) {
            int r = i2 >> 4, c = (i2 & 15) * 2;
            float2 v = gf[i2];
            *(float2*)(sS + r * MA + c) = v;
            ge[i2] = v;
            float* o = out + (btL * N + r) * (N + 1) + 1 + c;
            o[0] = v.x; o[1] = v.y;
        }
        if (tid < N) {
            float v = g_muf[btL * N + tid];
            smu[tid] = v;
            g_emu[((size_t)b * NCH + (NCH - 1)) * N + tid] = v;
            out[(btL * N + tid) * (N + 1)] = v;
        }
    }
    __syncthreads();

    for (int k = NCH - 2; k >= 0; k--) {
        const size_t obase = (size_t)b * NCH + (k + 1);
        {
            const float2* gx = (const float2*)(g_OX + obase * (N * N));
            const float2* gm = (const float2*)(g_OM + obase * (N * N));
            for (int i2 = tid; i2 < 512; i2 += 256) {
                int r = i2 >> 4, c = (i2 & 15) * 2;
                *(float2*)(sX + r * MA + c) = gx[i2];
                *(float2*)(sMm + r * MA + c) = gm[i2];
            }
            if (tid < N) sc[tid] = g_Oc[obase * N + tid];
        }
        __syncthreads();

        {
            const float2* Sr0 = (const float2*)(sS + r0 * MA);
            const float2* Sr1 = (const float2*)(sS + (r0 + 1) * MA);
            float a00 = 0, a01 = 0, a10 = 0, a11 = 0;
            #pragma unroll
            for (int k2 = 0; k2 < 16; k2++) {
                float2 x0 = Sr0[k2], x1 = Sr1[k2];
                float2 y0 = *(const float2*)(sX + (2 * k2) * MA + c0);
                float2 y1 = *(const float2*)(sX + (2 * k2 + 1) * MA + c0);
                a00 += x0.x * y0.x + x0.y * y1.x;  a01 += x0.x * y0.y + x0.y * y1.y;
                a10 += x1.x * y0.x + x1.y * y1.x;  a11 += x1.x * y0.y + x1.y * y1.y;
            }
            *(float2*)(sW + r0 * MA + c0) = make_float2(a00, a01);
            *(float2*)(sW + (r0 + 1) * MA + c0) = make_float2(a10, a11);
        }
        if (tid < N) {
            float s = sc[tid];
            #pragma unroll
            for (int j = 0; j < N; j++) s += sX[j * MA + tid] * smu[j];
            smuN[tid] = s;
        }
        __syncthreads();

        {
            float2 f0 = *(const float2*)(sMm + r0 * MA + c0);
            float2 f1 = *(const float2*)(sMm + (r0 + 1) * MA + c0);
            float a00 = f0.x, a01 = f0.y, a10 = f1.x, a11 = f1.y;
            #pragma unroll
            for (int j = 0; j < N; j++) {
                float2 xj = *(const float2*)(sX + j * MA + r0);
                float2 wj = *(const float2*)(sW + j * MA + c0);
                a00 += xj.x * wj.x;  a01 += xj.x * wj.y;
                a10 += xj.y * wj.x;  a11 += xj.y * wj.y;
            }
            *(float2*)(sS + r0 * MA + c0) = make_float2(a00, a01);
            *(float2*)(sS + (r0 + 1) * MA + c0) = make_float2(a10, a11);
            float* ge = g_eS + ((size_t)b * NCH + k) * (N * N);
            *(float2*)(ge + r0 * 32 + c0) = make_float2(a00, a01);
            *(float2*)(ge + (r0 + 1) * 32 + c0) = make_float2(a10, a11);
        }
        if (tid < N) {
            smu[tid] = smuN[tid];
            g_emu[((size_t)b * NCH + k) * N + tid] = smuN[tid];
        }
        __syncthreads();
    }
}

// =====================================================================
// Kernel 5 (Phase C): per-chunk backward recursion. grid (16, 64), 256 thr.
// =====================================================================
__global__ __launch_bounds__(256) void k_scanC(float* __restrict__ out)
{
    const int k = blockIdx.x, b = blockIdx.y;
    const int t_lo = CHS * k;
    const int t_hi = (k == NCH - 1) ? (T - 2) : (CHS * k + CHS - 1);
    const int tid = threadIdx.x;

    __shared__ __align__(16) float sS[NMA], sW[NMA];
    __shared__ __align__(16) float sX[2][NMA], sMm[2][NMA];
    __shared__ float smu[N], smuN[N], sc[2][N];

    const int r0 = (tid >> 4) * 2, c0 = (tid & 15) * 2;
    const int ra = tid >> 4, ca = (tid & 15) * 2;
    const int rb = ra + 16;

    {
        const size_t ebase = (size_t)b * NCH + k;
        const float2* ge = (const float2*)(g_eS + ebase * (N * N));
        for (int i2 = tid; i2 < 512; i2 += 256) {
            int r = i2 >> 4, c = (i2 & 15) * 2;
            *(float2*)(sS + r * MA + c) = ge[i2];
        }
        if (tid < N) smu[tid] = g_emu[ebase * N + tid];
    }

    float2 pX0, pX1, pM0, pM1;
    float pc = 0.f;
    {
        const size_t base = (size_t)b * (T - 1) + t_hi;
        const float2* gx = (const float2*)(g_J + base * (N * N));
        const float2* gm = (const float2*)(g_M + base * (N * N));
        pX0 = gx[tid];  pX1 = gx[tid + 256];
        pM0 = gm[tid];  pM1 = gm[tid + 256];
        if (tid < N) pc = g_c[base * N + tid];
    }
    __syncthreads();

    for (int t = t_hi; t >= t_lo; t--) {
        const int buf = (t_hi - t) & 1;
        const size_t bt = (size_t)b * T + t;
        *(float2*)(sX[buf] + ra * MA + ca) = pX0;
        *(float2*)(sX[buf] + rb * MA + ca) = pX1;
        *(float2*)(sMm[buf] + ra * MA + ca) = pM0;
        *(float2*)(sMm[buf] + rb * MA + ca) = pM1;
        if (tid < N) sc[buf][tid] = pc;
        if (t > t_lo) {
            const size_t base = (size_t)b * (T - 1) + (t - 1);
            const float2* gx = (const float2*)(g_J + base * (N * N));
            const float2* gm = (const float2*)(g_M + base * (N * N));
            pX0 = gx[tid];  pX1 = gx[tid + 256];
            pM0 = gm[tid];  pM1 = gm[tid + 256];
            if (tid < N) pc = g_c[base * N + tid];
        }
        __syncthreads();

        const float* Xb = sX[buf];
        const float* Mb = sMm[buf];

        {
            const float2* Sr0 = (const float2*)(sS + r0 * MA);
            const float2* Sr1 = (const float2*)(sS + (r0 + 1) * MA);
            float a00 = 0, a01 = 0, a10 = 0, a11 = 0;
            #pragma unroll
            for (int k2 = 0; k2 < 16; k2++) {
                float2 x0 = Sr0[k2], x1 = Sr1[k2];
                float2 y0 = *(const float2*)(Xb + (2 * k2) * MA + c0);
                float2 y1 = *(const float2*)(Xb + (2 * k2 + 1) * MA + c0);
                a00 += x0.x * y0.x + x0.y * y1.x;  a01 += x0.x * y0.y + x0.y * y1.y;
                a10 += x1.x * y0.x + x1.y * y1.x;  a11 += x1.x * y0.y + x1.y * y1.y;
            }
            *(float2*)(sW + r0 * MA + c0) = make_float2(a00, a01);
            *(float2*)(sW + (r0 + 1) * MA + c0) = make_float2(a10, a11);
        }
        if (tid < N) {
            float s = sc[buf][tid];
            #pragma unroll
            for (int j = 0; j < N; j++) s += Xb[j * MA + tid] * smu[j];
            smuN[tid] = s;
        }
        __syncthreads();

        {
            float2 f0 = *(const float2*)(Mb + r0 * MA + c0);
            float2 f1 = *(const float2*)(Mb + (r0 + 1) * MA + c0);
            float a00 = f0.x, a01 = f0.y, a10 = f1.x, a11 = f1.y;
            #pragma unroll
            for (int j = 0; j < N; j++) {
                float2 xj = *(const float2*)(Xb + j * MA + r0);
                float2 wj = *(const float2*)(sW + j * MA + c0);
                a00 += xj.x * wj.x;  a01 += xj.x * wj.y;
                a10 += xj.y * wj.x;  a11 += xj.y * wj.y;
            }
            *(float2*)(sS + r0 * MA + c0) = make_float2(a00, a01);
            *(float2*)(sS + (r0 + 1) * MA + c0) = make_float2(a10, a11);
            float* o = out + (bt * N + r0) * (N + 1) + 1 + c0;
            o[0] = a00; o[1] = a01;
            o[N + 1] = a10; o[N + 2] = a11;
        }
        if (tid < N) {
            smu[tid] = smuN[tid];
            out[(bt * N + tid) * (N + 1)] = smuN[tid];
        }
        __syncthreads();
    }
}

extern "C" void kernel_launch(void* const* d_in, const int* in_sizes, int n_in,
                              void* d_out, int out_size) {
    (void)in_sizes; (void)n_in; (void)out_size;
    const float* Y   = (const float*)d_in[0];
    const float* U   = (const float*)d_in[1];
    const float* A   = (const float*)d_in[2];
    const float* Bm  = (const float*)d_in[3];
    const float* C   = (const float*)d_in[4];
    const float* mu0 = (const float*)d_in[5];
    const float* S0  = (const float*)d_in[6];
    float* out = (float*)d_out;

    k_main<<<148, 512>>>(Y, U, A, Bm, C, mu0, S0);
    k_scanA<<<dim3(NCH, BATCH), 256>>>();
    k_scanB<<<BATCH, 256>>>(out);
    k_scanC<<<dim3(NCH, BATCH), 256>>>(out);
}